// round 1
// baseline (speedup 1.0000x reference)
#include <cuda_runtime.h>
#include <math.h>

#define BATCH 8
#define CC    64
#define CHN   192
#define ICH   96
#define HWPX  16384
#define EPSV  1e-5f
#define TM    64

// ---- device scratch (no allocations allowed) ----
__device__ float g_W1[ICH * CHN], g_B1[ICH];
__device__ float g_W2[CHN * ICH], g_B2[CHN];
__device__ float g_GW1[ICH * CHN], g_GB1[ICH];
__device__ float g_GW2[CHN * ICH], g_GB2[CHN];
__device__ float g_gap[BATCH * CHN];
__device__ float g_xg[BATCH * CHN];

// Fold eval-mode BN into conv weights/bias.
// which: 0 -> g_W1/g_B1, 1 -> g_W2/g_B2, 2 -> g_GW1/g_GB1, 3 -> g_GW2/g_GB2
__global__ void fold_kernel(const float* __restrict__ w, const float* __restrict__ b,
                            const float* __restrict__ g, const float* __restrict__ be,
                            const float* __restrict__ m, const float* __restrict__ v,
                            int O, int K, int which) {
    float* Weff = (which == 0) ? g_W1 : (which == 1) ? g_W2 : (which == 2) ? g_GW1 : g_GW2;
    float* beff = (which == 0) ? g_B1 : (which == 1) ? g_B2 : (which == 2) ? g_GB1 : g_GB2;
    int total = O * K;
    for (int idx = blockIdx.x * blockDim.x + threadIdx.x; idx < total;
         idx += gridDim.x * blockDim.x) {
        int o = idx / K;
        float s = g[o] / sqrtf(v[o] + EPSV);
        Weff[idx] = w[idx] * s;
        if (idx - o * K == 0) beff[o] = (b[o] - m[o]) * s + be[o];
    }
}

// Global average pool: mean over HW per (batch, concat-channel)
__global__ void gap_kernel(const float* __restrict__ x1, const float* __restrict__ x2,
                           const float* __restrict__ x3) {
    int ch = blockIdx.x;   // 0..191
    int b  = blockIdx.y;   // 0..7
    const float* x = (ch < 64) ? x1 : (ch < 128) ? x2 : x3;
    int cc = ch & 63;
    const float* p = x + ((size_t)(b * CC + cc)) * HWPX;
    float s = 0.f;
    for (int i = threadIdx.x; i < HWPX; i += blockDim.x) s += p[i];
#pragma unroll
    for (int off = 16; off; off >>= 1) s += __shfl_down_sync(0xFFFFFFFFu, s, off);
    __shared__ float sm[8];
    if ((threadIdx.x & 31) == 0) sm[threadIdx.x >> 5] = s;
    __syncthreads();
    if (threadIdx.x == 0) {
        float t = 0.f;
#pragma unroll
        for (int w = 0; w < 8; w++) t += sm[w];
        g_gap[b * CHN + ch] = t * (1.f / (float)HWPX);
    }
}

// Global attention MLP (per batch): xg = bn2(W2 @ relu(bn1(W1 @ gap + b1)) + b2), folded.
__global__ void gmlp_kernel() {
    int b = blockIdx.x;
    int t = threadIdx.x;   // 0..191
    __shared__ float v[CHN];
    __shared__ float h[ICH];
    v[t] = g_gap[b * CHN + t];
    __syncthreads();
    if (t < ICH) {
        float acc = g_GB1[t];
        const float* wr = g_GW1 + t * CHN;
#pragma unroll 4
        for (int c = 0; c < CHN; c++) acc = fmaf(wr[c], v[c], acc);
        h[t] = fmaxf(acc, 0.f);
    }
    __syncthreads();
    {
        float acc = g_GB2[t];
        const float* wr = g_GW2 + t * ICH;
#pragma unroll 4
        for (int c = 0; c < ICH; c++) acc = fmaf(wr[c], h[c], acc);
        g_xg[b * CHN + t] = acc;
    }
}

// Fused main kernel: per 64-pixel tile, local attention branch (2 GEMMs),
// add global branch, sigmoid, softmax-over-3-groups, weighted sum of x1/x2/x3.
// SMEM layout (floats):
//   Xs  [192][64]          = 12288
//   W1s [96][193] (padded) = 18528
//   W2s [192][97] (padded) = 18624
//   Hs  [96][64]           =  6144
#define SM_FLOATS (12288 + 18528 + 18624 + 6144)

__global__ __launch_bounds__(256, 1)
void main_kernel(const float* __restrict__ x1, const float* __restrict__ x2,
                 const float* __restrict__ x3, float* __restrict__ out) {
    extern __shared__ float sm[];
    float* Xs  = sm;
    float* W1s = Xs + CHN * TM;
    float* W2s = W1s + ICH * 193;
    float* Hs  = W2s + CHN * 97;

    int tid = threadIdx.x;
    int P   = blockIdx.x * TM;
    int b   = P / HWPX;
    int hw0 = P - b * HWPX;

    // load X tile [192 ch][64 px], coalesced
    for (int idx = tid; idx < CHN * TM; idx += 256) {
        int ch = idx >> 6;
        int px = idx & 63;
        const float* x = (ch < 64) ? x1 : (ch < 128) ? x2 : x3;
        int cc = ch & 63;
        Xs[idx] = x[((size_t)(b * CC + cc)) * HWPX + hw0 + px];
    }
    // load folded weights into padded smem
    for (int idx = tid; idx < ICH * CHN; idx += 256) {
        int o = idx / CHN;
        int k = idx - o * CHN;
        W1s[o * 193 + k] = g_W1[idx];
    }
    for (int idx = tid; idx < CHN * ICH; idx += 256) {
        int n = idx / ICH;
        int k = idx - n * ICH;
        W2s[n * 97 + k] = g_W2[idx];
    }
    __syncthreads();

    int pxt = tid & 15;   // pixel group: px = pxt*4 + {0..3}
    int nt  = tid >> 4;   // 0..15

    // ---- GEMM1: H[96][64] = relu(W1eff @ X + b1eff); thread = 4 px x 6 outs ----
    {
        float acc1[6][4];
#pragma unroll
        for (int i = 0; i < 6; i++)
#pragma unroll
            for (int j = 0; j < 4; j++) acc1[i][j] = 0.f;

        const float* W1base = W1s + (nt * 6) * 193;
        const float* Xbase  = Xs + (pxt << 2);
#pragma unroll 4
        for (int k = 0; k < CHN; k++) {
            float4 a = *(const float4*)(Xbase + (k << 6));
#pragma unroll
            for (int ni = 0; ni < 6; ni++) {
                float w = W1base[ni * 193 + k];
                acc1[ni][0] = fmaf(w, a.x, acc1[ni][0]);
                acc1[ni][1] = fmaf(w, a.y, acc1[ni][1]);
                acc1[ni][2] = fmaf(w, a.z, acc1[ni][2]);
                acc1[ni][3] = fmaf(w, a.w, acc1[ni][3]);
            }
        }
#pragma unroll
        for (int ni = 0; ni < 6; ni++) {
            int n = nt * 6 + ni;
            float bb = g_B1[n];
            float* hrow = Hs + (n << 6) + (pxt << 2);
#pragma unroll
            for (int pi = 0; pi < 4; pi++) hrow[pi] = fmaxf(acc1[ni][pi] + bb, 0.f);
        }
    }
    __syncthreads();

    // ---- GEMM2 + epilogue: thread = 4 px x channels {c0..c0+3} across all 3 groups ----
    {
        int c0 = nt * 4;   // 0..60
        float acc[12][4];  // [gg*4+j][pi]
#pragma unroll
        for (int gg = 0; gg < 3; gg++)
#pragma unroll
            for (int j = 0; j < 4; j++) {
                int n = c0 + j + 64 * gg;
                float base = g_B2[n] + g_xg[b * CHN + n];
#pragma unroll
                for (int pi = 0; pi < 4; pi++) acc[gg * 4 + j][pi] = base;
            }

        const float* W2base = W2s + c0 * 97;
        const float* Hbase  = Hs + (pxt << 2);
#pragma unroll 2
        for (int k = 0; k < ICH; k++) {
            float4 a = *(const float4*)(Hbase + (k << 6));
#pragma unroll
            for (int gg = 0; gg < 3; gg++)
#pragma unroll
                for (int j = 0; j < 4; j++) {
                    float w = W2base[(j + 64 * gg) * 97 + k];
                    float* ac = acc[gg * 4 + j];
                    ac[0] = fmaf(w, a.x, ac[0]);
                    ac[1] = fmaf(w, a.y, ac[1]);
                    ac[2] = fmaf(w, a.z, ac[2]);
                    ac[3] = fmaf(w, a.w, ac[3]);
                }
        }

        // sigmoid -> softmax over 3 groups -> weighted sum of x's
#pragma unroll
        for (int j = 0; j < 4; j++) {
            int c = c0 + j;
            float res[4];
#pragma unroll
            for (int pi = 0; pi < 4; pi++) {
                float s0 = 1.f / (1.f + __expf(-acc[0 + j][pi]));
                float s1 = 1.f / (1.f + __expf(-acc[4 + j][pi]));
                float s2 = 1.f / (1.f + __expf(-acc[8 + j][pi]));
                float e0 = __expf(s0), e1 = __expf(s1), e2 = __expf(s2);
                float xv0 = Xs[(c << 6) + (pxt << 2) + pi];
                float xv1 = Xs[((c + 64) << 6) + (pxt << 2) + pi];
                float xv2 = Xs[((c + 128) << 6) + (pxt << 2) + pi];
                res[pi] = (e0 * xv0 + e1 * xv1 + e2 * xv2) / (e0 + e1 + e2);
            }
            *(float4*)(out + ((size_t)(b * CC + c)) * HWPX + hw0 + (pxt << 2)) =
                make_float4(res[0], res[1], res[2], res[3]);
        }
    }
}

extern "C" void kernel_launch(void* const* d_in, const int* in_sizes, int n_in,
                              void* d_out, int out_size) {
    const float* x1 = (const float*)d_in[0];
    const float* x2 = (const float*)d_in[1];
    const float* x3 = (const float*)d_in[2];
    // local path params: indices 3..14, global path: 15..26
    const float* lw1 = (const float*)d_in[3];
    const float* lb1 = (const float*)d_in[4];
    const float* lg1 = (const float*)d_in[5];
    const float* lbe1 = (const float*)d_in[6];
    const float* lm1 = (const float*)d_in[7];
    const float* lv1 = (const float*)d_in[8];
    const float* lw2 = (const float*)d_in[9];
    const float* lb2 = (const float*)d_in[10];
    const float* lg2 = (const float*)d_in[11];
    const float* lbe2 = (const float*)d_in[12];
    const float* lm2 = (const float*)d_in[13];
    const float* lv2 = (const float*)d_in[14];
    const float* gw1 = (const float*)d_in[15];
    const float* gb1 = (const float*)d_in[16];
    const float* gg1 = (const float*)d_in[17];
    const float* gbe1 = (const float*)d_in[18];
    const float* gm1 = (const float*)d_in[19];
    const float* gv1 = (const float*)d_in[20];
    const float* gw2 = (const float*)d_in[21];
    const float* gb2 = (const float*)d_in[22];
    const float* gg2 = (const float*)d_in[23];
    const float* gbe2 = (const float*)d_in[24];
    const float* gm2 = (const float*)d_in[25];
    const float* gv2 = (const float*)d_in[26];
    float* out = (float*)d_out;

    cudaFuncSetAttribute(main_kernel, cudaFuncAttributeMaxDynamicSharedMemorySize,
                         SM_FLOATS * (int)sizeof(float));

    // BN folding (both paths)
    fold_kernel<<<72, 256>>>(lw1, lb1, lg1, lbe1, lm1, lv1, ICH, CHN, 0);
    fold_kernel<<<72, 256>>>(lw2, lb2, lg2, lbe2, lm2, lv2, CHN, ICH, 1);
    fold_kernel<<<72, 256>>>(gw1, gb1, gg1, gbe1, gm1, gv1, ICH, CHN, 2);
    fold_kernel<<<72, 256>>>(gw2, gb2, gg2, gbe2, gm2, gv2, CHN, ICH, 3);

    // global branch
    gap_kernel<<<dim3(CHN, BATCH), 256>>>(x1, x2, x3);
    gmlp_kernel<<<BATCH, CHN>>>();

    // fused local branch + combine
    int nblocks = (BATCH * HWPX) / TM;  // 2048
    main_kernel<<<nblocks, 256, SM_FLOATS * (int)sizeof(float)>>>(x1, x2, x3, out);
}

// round 2
// speedup vs baseline: 1.0050x; 1.0050x over previous
#include <cuda_runtime.h>
#include <math.h>

#define BATCH 8
#define CC    64
#define CHN   192
#define ICH   96
#define HWPX  16384
#define EPSV  1e-5f
#define TM    64

// ---- device scratch (no allocations allowed) ----
__device__ float g_W1[ICH * CHN], g_B1[ICH];
__device__ float g_W2[CHN * ICH], g_B2[CHN];
__device__ float g_GW1[ICH * CHN], g_GB1[ICH];
__device__ float g_GW2[CHN * ICH], g_GB2[CHN];
__device__ float g_gap[BATCH * CHN];
__device__ float g_xg[BATCH * CHN];

// Fold eval-mode BN into conv weights/bias.
// which: 0 -> g_W1/g_B1, 1 -> g_W2/g_B2, 2 -> g_GW1/g_GB1, 3 -> g_GW2/g_GB2
__global__ void fold_kernel(const float* __restrict__ w, const float* __restrict__ b,
                            const float* __restrict__ g, const float* __restrict__ be,
                            const float* __restrict__ m, const float* __restrict__ v,
                            int O, int K, int which) {
    float* Weff = (which == 0) ? g_W1 : (which == 1) ? g_W2 : (which == 2) ? g_GW1 : g_GW2;
    float* beff = (which == 0) ? g_B1 : (which == 1) ? g_B2 : (which == 2) ? g_GB1 : g_GB2;
    int total = O * K;
    for (int idx = blockIdx.x * blockDim.x + threadIdx.x; idx < total;
         idx += gridDim.x * blockDim.x) {
        int o = idx / K;
        float s = g[o] / sqrtf(v[o] + EPSV);
        Weff[idx] = w[idx] * s;
        if (idx - o * K == 0) beff[o] = (b[o] - m[o]) * s + be[o];
    }
}

// Global average pool: mean over HW per (batch, concat-channel)
__global__ void gap_kernel(const float* __restrict__ x1, const float* __restrict__ x2,
                           const float* __restrict__ x3) {
    int ch = blockIdx.x;   // 0..191
    int b  = blockIdx.y;   // 0..7
    const float* x = (ch < 64) ? x1 : (ch < 128) ? x2 : x3;
    int cc = ch & 63;
    const float* p = x + ((size_t)(b * CC + cc)) * HWPX;
    float s = 0.f;
    for (int i = threadIdx.x; i < HWPX; i += blockDim.x) s += p[i];
#pragma unroll
    for (int off = 16; off; off >>= 1) s += __shfl_down_sync(0xFFFFFFFFu, s, off);
    __shared__ float sm[8];
    if ((threadIdx.x & 31) == 0) sm[threadIdx.x >> 5] = s;
    __syncthreads();
    if (threadIdx.x == 0) {
        float t = 0.f;
#pragma unroll
        for (int w = 0; w < 8; w++) t += sm[w];
        g_gap[b * CHN + ch] = t * (1.f / (float)HWPX);
    }
}

// Global attention MLP (per batch): xg = bn2(W2 @ relu(bn1(W1 @ gap + b1)) + b2), folded.
__global__ void gmlp_kernel() {
    int b = blockIdx.x;
    int t = threadIdx.x;   // 0..191
    __shared__ float v[CHN];
    __shared__ float h[ICH];
    v[t] = g_gap[b * CHN + t];
    __syncthreads();
    if (t < ICH) {
        float acc = g_GB1[t];
        const float* wr = g_GW1 + t * CHN;
#pragma unroll 4
        for (int c = 0; c < CHN; c++) acc = fmaf(wr[c], v[c], acc);
        h[t] = fmaxf(acc, 0.f);
    }
    __syncthreads();
    {
        float acc = g_GB2[t];
        const float* wr = g_GW2 + t * ICH;
#pragma unroll 4
        for (int c = 0; c < ICH; c++) acc = fmaf(wr[c], h[c], acc);
        g_xg[b * CHN + t] = acc;
    }
}

// Fused main kernel: per 64-pixel tile, local attention branch (2 GEMMs),
// add global branch, sigmoid, softmax-over-3-groups, weighted sum of x1/x2/x3.
// SMEM layout (floats):
//   Xs  [192][64]          = 12288
//   W1s [96][193] (padded) = 18528
//   W2s [192][97] (padded) = 18624
//   Hs  [96][64]           =  6144
#define SM_FLOATS (12288 + 18528 + 18624 + 6144)

__global__ __launch_bounds__(256, 1)
void main_kernel(const float* __restrict__ x1, const float* __restrict__ x2,
                 const float* __restrict__ x3, float* __restrict__ out) {
    extern __shared__ float sm[];
    float* Xs  = sm;
    float* W1s = Xs + CHN * TM;
    float* W2s = W1s + ICH * 193;
    float* Hs  = W2s + CHN * 97;

    int tid = threadIdx.x;
    int P   = blockIdx.x * TM;
    int b   = P / HWPX;
    int hw0 = P - b * HWPX;

    // load X tile [192 ch][64 px], coalesced
    for (int idx = tid; idx < CHN * TM; idx += 256) {
        int ch = idx >> 6;
        int px = idx & 63;
        const float* x = (ch < 64) ? x1 : (ch < 128) ? x2 : x3;
        int cc = ch & 63;
        Xs[idx] = x[((size_t)(b * CC + cc)) * HWPX + hw0 + px];
    }
    // load folded weights into padded smem
    for (int idx = tid; idx < ICH * CHN; idx += 256) {
        int o = idx / CHN;
        int k = idx - o * CHN;
        W1s[o * 193 + k] = g_W1[idx];
    }
    for (int idx = tid; idx < CHN * ICH; idx += 256) {
        int n = idx / ICH;
        int k = idx - n * ICH;
        W2s[n * 97 + k] = g_W2[idx];
    }
    __syncthreads();

    int pxt = tid & 15;   // pixel group: px = pxt*4 + {0..3}
    int nt  = tid >> 4;   // 0..15

    // ---- GEMM1: H[96][64] = relu(W1eff @ X + b1eff); thread = 4 px x 6 outs ----
    {
        float acc1[6][4];
#pragma unroll
        for (int i = 0; i < 6; i++)
#pragma unroll
            for (int j = 0; j < 4; j++) acc1[i][j] = 0.f;

        const float* W1base = W1s + (nt * 6) * 193;
        const float* Xbase  = Xs + (pxt << 2);
#pragma unroll 4
        for (int k = 0; k < CHN; k++) {
            float4 a = *(const float4*)(Xbase + (k << 6));
#pragma unroll
            for (int ni = 0; ni < 6; ni++) {
                float w = W1base[ni * 193 + k];
                acc1[ni][0] = fmaf(w, a.x, acc1[ni][0]);
                acc1[ni][1] = fmaf(w, a.y, acc1[ni][1]);
                acc1[ni][2] = fmaf(w, a.z, acc1[ni][2]);
                acc1[ni][3] = fmaf(w, a.w, acc1[ni][3]);
            }
        }
#pragma unroll
        for (int ni = 0; ni < 6; ni++) {
            int n = nt * 6 + ni;
            float bb = g_B1[n];
            float* hrow = Hs + (n << 6) + (pxt << 2);
#pragma unroll
            for (int pi = 0; pi < 4; pi++) hrow[pi] = fmaxf(acc1[ni][pi] + bb, 0.f);
        }
    }
    __syncthreads();

    // ---- GEMM2 + epilogue: thread = 4 px x channels {c0..c0+3} across all 3 groups ----
    {
        int c0 = nt * 4;   // 0..60
        float acc[12][4];  // [gg*4+j][pi]
#pragma unroll
        for (int gg = 0; gg < 3; gg++)
#pragma unroll
            for (int j = 0; j < 4; j++) {
                int n = c0 + j + 64 * gg;
                float base = g_B2[n] + g_xg[b * CHN + n];
#pragma unroll
                for (int pi = 0; pi < 4; pi++) acc[gg * 4 + j][pi] = base;
            }

        const float* W2base = W2s + c0 * 97;
        const float* Hbase  = Hs + (pxt << 2);
#pragma unroll 2
        for (int k = 0; k < ICH; k++) {
            float4 a = *(const float4*)(Hbase + (k << 6));
#pragma unroll
            for (int gg = 0; gg < 3; gg++)
#pragma unroll
                for (int j = 0; j < 4; j++) {
                    float w = W2base[(j + 64 * gg) * 97 + k];
                    float* ac = acc[gg * 4 + j];
                    ac[0] = fmaf(w, a.x, ac[0]);
                    ac[1] = fmaf(w, a.y, ac[1]);
                    ac[2] = fmaf(w, a.z, ac[2]);
                    ac[3] = fmaf(w, a.w, ac[3]);
                }
        }

        // sigmoid -> softmax over 3 groups -> weighted sum of x's
#pragma unroll
        for (int j = 0; j < 4; j++) {
            int c = c0 + j;
            float res[4];
#pragma unroll
            for (int pi = 0; pi < 4; pi++) {
                float s0 = 1.f / (1.f + __expf(-acc[0 + j][pi]));
                float s1 = 1.f / (1.f + __expf(-acc[4 + j][pi]));
                float s2 = 1.f / (1.f + __expf(-acc[8 + j][pi]));
                float e0 = __expf(s0), e1 = __expf(s1), e2 = __expf(s2);
                float xv0 = Xs[(c << 6) + (pxt << 2) + pi];
                float xv1 = Xs[((c + 64) << 6) + (pxt << 2) + pi];
                float xv2 = Xs[((c + 128) << 6) + (pxt << 2) + pi];
                res[pi] = (e0 * xv0 + e1 * xv1 + e2 * xv2) / (e0 + e1 + e2);
            }
            *(float4*)(out + ((size_t)(b * CC + c)) * HWPX + hw0 + (pxt << 2)) =
                make_float4(res[0], res[1], res[2], res[3]);
        }
    }
}

extern "C" void kernel_launch(void* const* d_in, const int* in_sizes, int n_in,
                              void* d_out, int out_size) {
    const float* x1 = (const float*)d_in[0];
    const float* x2 = (const float*)d_in[1];
    const float* x3 = (const float*)d_in[2];
    // local path params: indices 3..14, global path: 15..26
    const float* lw1 = (const float*)d_in[3];
    const float* lb1 = (const float*)d_in[4];
    const float* lg1 = (const float*)d_in[5];
    const float* lbe1 = (const float*)d_in[6];
    const float* lm1 = (const float*)d_in[7];
    const float* lv1 = (const float*)d_in[8];
    const float* lw2 = (const float*)d_in[9];
    const float* lb2 = (const float*)d_in[10];
    const float* lg2 = (const float*)d_in[11];
    const float* lbe2 = (const float*)d_in[12];
    const float* lm2 = (const float*)d_in[13];
    const float* lv2 = (const float*)d_in[14];
    const float* gw1 = (const float*)d_in[15];
    const float* gb1 = (const float*)d_in[16];
    const float* gg1 = (const float*)d_in[17];
    const float* gbe1 = (const float*)d_in[18];
    const float* gm1 = (const float*)d_in[19];
    const float* gv1 = (const float*)d_in[20];
    const float* gw2 = (const float*)d_in[21];
    const float* gb2 = (const float*)d_in[22];
    const float* gg2 = (const float*)d_in[23];
    const float* gbe2 = (const float*)d_in[24];
    const float* gm2 = (const float*)d_in[25];
    const float* gv2 = (const float*)d_in[26];
    float* out = (float*)d_out;

    cudaFuncSetAttribute(main_kernel, cudaFuncAttributeMaxDynamicSharedMemorySize,
                         SM_FLOATS * (int)sizeof(float));

    // BN folding (both paths)
    fold_kernel<<<72, 256>>>(lw1, lb1, lg1, lbe1, lm1, lv1, ICH, CHN, 0);
    fold_kernel<<<72, 256>>>(lw2, lb2, lg2, lbe2, lm2, lv2, CHN, ICH, 1);
    fold_kernel<<<72, 256>>>(gw1, gb1, gg1, gbe1, gm1, gv1, ICH, CHN, 2);
    fold_kernel<<<72, 256>>>(gw2, gb2, gg2, gbe2, gm2, gv2, CHN, ICH, 3);

    // global branch
    gap_kernel<<<dim3(CHN, BATCH), 256>>>(x1, x2, x3);
    gmlp_kernel<<<BATCH, CHN>>>();

    // fused local branch + combine
    int nblocks = (BATCH * HWPX) / TM;  // 2048
    main_kernel<<<nblocks, 256, SM_FLOATS * (int)sizeof(float)>>>(x1, x2, x3, out);
}

// round 4
// speedup vs baseline: 3.3694x; 3.3526x over previous
#include <cuda_runtime.h>
#include <cuda_bf16.h>
#include <cstdint>

#define BATCH 8
#define HWPX  16384
#define EPSV  1e-5f
#define NCTA  148
#define NTILES 2048

// smem element strides (bf16 elems) chosen for ldmatrix bank spread + 16B row align
#define STW1 200   // W1s [96][192] pad->200   (400B rows)
#define STW2 104   // W2s [192][96] pad->104   (208B rows)
#define STX  80    // Xs  [192][64] pad->80    (160B rows)
#define STH  80    // Hs  [96][64]  pad->80

// byte offsets in dynamic smem
#define SM_W1 0                       // 96*200*2  = 38400
#define SM_W2 38400                   // 192*104*2 = 39936
#define SM_X  78336                   // 192*80*2  = 30720
#define SM_H  109056                  // 96*80*2   = 15360
#define SM_XF 124416                  // 192*64*4  = 49152
#define SM_B1 173568                  // 96*4      = 384
#define SM_B2 173952                  // 192*4     = 768
#define SM_XG 174720                  // 192*4     = 768
#define DSZ   175488

// ------------------- warp MMA primitives (sm_80+, legal on compute_103) -------------------
__device__ __forceinline__ uint32_t smem_u32(const void* p) {
    uint32_t a;
    asm("{ .reg .u64 t; cvta.to.shared.u64 t, %1; cvt.u32.u64 %0, t; }" : "=r"(a) : "l"(p));
    return a;
}
__device__ __forceinline__ void ldsm4(uint32_t (&r)[4], uint32_t addr) {
    asm volatile("ldmatrix.sync.aligned.m8n8.x4.shared.b16 {%0,%1,%2,%3}, [%4];"
                 : "=r"(r[0]), "=r"(r[1]), "=r"(r[2]), "=r"(r[3]) : "r"(addr));
}
__device__ __forceinline__ void ldsm2t(uint32_t (&r)[2], uint32_t addr) {
    asm volatile("ldmatrix.sync.aligned.m8n8.x2.trans.shared.b16 {%0,%1}, [%2];"
                 : "=r"(r[0]), "=r"(r[1]) : "r"(addr));
}
__device__ __forceinline__ void mma16816(float (&d)[4], const uint32_t (&a)[4],
                                         const uint32_t (&b)[2]) {
    asm volatile("mma.sync.aligned.m16n8k16.row.col.f32.bf16.bf16.f32 "
                 "{%0,%1,%2,%3}, {%4,%5,%6,%7}, {%8,%9}, {%0,%1,%2,%3};"
                 : "+f"(d[0]), "+f"(d[1]), "+f"(d[2]), "+f"(d[3])
                 : "r"(a[0]), "r"(a[1]), "r"(a[2]), "r"(a[3]), "r"(b[0]), "r"(b[1]));
}
__device__ __forceinline__ float sigm(float v) {
    return __fdividef(1.f, 1.f + __expf(-v));
}
// exp(s), s in (0,1): e^0.5 * Taylor(u=s-0.5), rel err < 2e-5, FMA-only
__device__ __forceinline__ float exp01(float s) {
    float u = s - 0.5f;
    float p = 8.3333333e-3f;
    p = fmaf(p, u, 4.1666667e-2f);
    p = fmaf(p, u, 0.16666667f);
    p = fmaf(p, u, 0.5f);
    p = fmaf(p, u, 1.0f);
    p = fmaf(p, u, 1.0f);
    return 1.64872127f * p;
}

// ------------------------- globals -------------------------
__device__ float g_gap[BATCH * 192];
__device__ float g_xg[BATCH * 192];

// ------------------------- GAP -------------------------
__global__ void gap_kernel(const float* __restrict__ x1, const float* __restrict__ x2,
                           const float* __restrict__ x3) {
    int ch = blockIdx.x, b = blockIdx.y;
    const float* x = (ch < 64) ? x1 : (ch < 128) ? x2 : x3;
    const float* p = x + ((size_t)(b * 64 + (ch & 63))) * HWPX;
    float s = 0.f;
    for (int i = threadIdx.x * 4; i < HWPX; i += 1024) {
        float4 v = *(const float4*)(p + i);
        s += (v.x + v.y) + (v.z + v.w);
    }
#pragma unroll
    for (int off = 16; off; off >>= 1) s += __shfl_down_sync(0xFFFFFFFFu, s, off);
    __shared__ float sm[8];
    if ((threadIdx.x & 31) == 0) sm[threadIdx.x >> 5] = s;
    __syncthreads();
    if (threadIdx.x == 0) {
        float t = 0.f;
#pragma unroll
        for (int w = 0; w < 8; w++) t += sm[w];
        g_gap[b * 192 + ch] = t * (1.f / (float)HWPX);
    }
}

// ------------------------- global-branch MLP -------------------------
__global__ void gmlp_kernel(const float* __restrict__ gw1, const float* __restrict__ gb1,
                            const float* __restrict__ gg1, const float* __restrict__ gbe1,
                            const float* __restrict__ gm1, const float* __restrict__ gv1,
                            const float* __restrict__ gw2, const float* __restrict__ gb2,
                            const float* __restrict__ gg2, const float* __restrict__ gbe2,
                            const float* __restrict__ gm2, const float* __restrict__ gv2) {
    int b = blockIdx.x, t = threadIdx.x;
    __shared__ float v[192], h[96];
    v[t] = g_gap[b * 192 + t];
    __syncthreads();
    if (t < 96) {
        float a = gb1[t];
        const float* w = gw1 + t * 192;
#pragma unroll 4
        for (int c = 0; c < 192; c++) a = fmaf(w[c], v[c], a);
        float s = gg1[t] * rsqrtf(gv1[t] + EPSV);
        h[t] = fmaxf(fmaf(a - gm1[t], s, gbe1[t]), 0.f);
    }
    __syncthreads();
    {
        float a = gb2[t];
        const float* w = gw2 + t * 96;
#pragma unroll 4
        for (int c = 0; c < 96; c++) a = fmaf(w[c], h[c], a);
        float s = gg2[t] * rsqrtf(gv2[t] + EPSV);
        g_xg[b * 192 + t] = fmaf(a - gm2[t], s, gbe2[t]);
    }
}

// ------------------------- fused main kernel -------------------------
__global__ __launch_bounds__(256, 1)
void main_kernel(const float* __restrict__ x1, const float* __restrict__ x2,
                 const float* __restrict__ x3,
                 const float* __restrict__ lw1, const float* __restrict__ lb1,
                 const float* __restrict__ lg1, const float* __restrict__ lbe1,
                 const float* __restrict__ lm1, const float* __restrict__ lv1,
                 const float* __restrict__ lw2, const float* __restrict__ lb2,
                 const float* __restrict__ lg2, const float* __restrict__ lbe2,
                 const float* __restrict__ lm2, const float* __restrict__ lv2,
                 float* __restrict__ out) {
    extern __shared__ char dsm[];
    const uint32_t SB = smem_u32(dsm);

    int tid = threadIdx.x;
    int wid = tid >> 5, lane = tid & 31;
    int qrow = lane >> 2;          // 0..7
    int qcol = lane & 3;           // 0..3
    int lsrow = lane & 15;         // ldmatrix row provider
    int lscol = (lane >> 4) << 3;  // 0 or 8
    int n0 = wid << 3;             // this warp's px strip base

    float* XF  = (float*)(dsm + SM_XF);
    float* B1s = (float*)(dsm + SM_B1);
    float* B2s = (float*)(dsm + SM_B2);
    float* Xg  = (float*)(dsm + SM_XG);

    // ---- prologue: fold BN into bf16 weights in smem (once per CTA) ----
    for (int i = tid; i < 96 * 192; i += 256) {
        int o = i / 192, k = i - o * 192;
        float sc = lg1[o] * rsqrtf(lv1[o] + EPSV);
        *(__nv_bfloat16*)(dsm + SM_W1 + (o * STW1 + k) * 2) = __float2bfloat16_rn(lw1[i] * sc);
        if (k == 0) B1s[o] = fmaf(lb1[o] - lm1[o], sc, lbe1[o]);
    }
    for (int i = tid; i < 192 * 96; i += 256) {
        int o = i / 96, k = i - o * 96;
        float sc = lg2[o] * rsqrtf(lv2[o] + EPSV);
        *(__nv_bfloat16*)(dsm + SM_W2 + (o * STW2 + k) * 2) = __float2bfloat16_rn(lw2[i] * sc);
        if (k == 0) B2s[o] = fmaf(lb2[o] - lm2[o], sc, lbe2[o]);
    }
    __syncthreads();

    const uint32_t W1S = SB + SM_W1, W2S = SB + SM_W2, XS = SB + SM_X, HS = SB + SM_H;

    for (int T = blockIdx.x; T < NTILES; T += NCTA) {
        int b = T >> 8;
        int hw0 = (T & 255) << 6;

        // ---- load X tile: fp32 -> XF, bf16 -> Xs; also Xg = B2 + global logits ----
#pragma unroll
        for (int j = 0; j < 12; j++) {
            int fidx = (tid + j * 256) * 4;
            int ch = fidx >> 6, px = fidx & 63;
            const float* xp = (ch < 64) ? x1 : (ch < 128) ? x2 : x3;
            float4 v = *(const float4*)(xp + ((size_t)((b << 6) + (ch & 63))) * HWPX + hw0 + px);
            *(float4*)(XF + fidx) = v;
            __nv_bfloat162 p0 = __floats2bfloat162_rn(v.x, v.y);
            __nv_bfloat162 p1 = __floats2bfloat162_rn(v.z, v.w);
            *(uint2*)(dsm + SM_X + (ch * STX + px) * 2) =
                make_uint2(*(uint32_t*)&p0, *(uint32_t*)&p1);
        }
        if (tid < 192) Xg[tid] = B2s[tid] + g_xg[b * 192 + tid];
        __syncthreads();

        // ---- GEMM1: C1[96ch][8px] per warp, K=192 ----
        uint32_t bfr[12][2];
#pragma unroll
        for (int kt = 0; kt < 12; kt++)
            ldsm2t(bfr[kt], XS + ((16 * kt + lsrow) * STX + n0) * 2);

        float acc1[6][4];
#pragma unroll
        for (int mt = 0; mt < 6; mt++) {
#pragma unroll
            for (int i = 0; i < 4; i++) acc1[mt][i] = 0.f;
#pragma unroll
            for (int kt = 0; kt < 12; kt++) {
                uint32_t a[4];
                ldsm4(a, W1S + ((16 * mt + lsrow) * STW1 + 16 * kt + lscol) * 2);
                mma16816(acc1[mt], a, bfr[kt]);
            }
        }

        // ---- epilogue1: bias + relu -> Hs[ch][px] bf16 (own px cols only) ----
#pragma unroll
        for (int mt = 0; mt < 6; mt++) {
            int ca = 16 * mt + qrow;
            int pxb = n0 + 2 * qcol;
            float ba = B1s[ca], bb = B1s[ca + 8];
            __nv_bfloat162 ha = __floats2bfloat162_rn(fmaxf(acc1[mt][0] + ba, 0.f),
                                                      fmaxf(acc1[mt][1] + ba, 0.f));
            __nv_bfloat162 hb = __floats2bfloat162_rn(fmaxf(acc1[mt][2] + bb, 0.f),
                                                      fmaxf(acc1[mt][3] + bb, 0.f));
            *(uint32_t*)(dsm + SM_H + (ca * STH + pxb) * 2) = *(uint32_t*)&ha;
            *(uint32_t*)(dsm + SM_H + ((ca + 8) * STH + pxb) * 2) = *(uint32_t*)&hb;
        }
        __syncwarp();

        // ---- GEMM2: C2[192ch][8px] per warp, K=96 ----
        uint32_t hfr[6][2];
#pragma unroll
        for (int kt = 0; kt < 6; kt++)
            ldsm2t(hfr[kt], HS + ((16 * kt + lsrow) * STH + n0) * 2);

        float acc2[12][4];
#pragma unroll
        for (int mt = 0; mt < 12; mt++) {
#pragma unroll
            for (int i = 0; i < 4; i++) acc2[mt][i] = 0.f;
#pragma unroll
            for (int kt = 0; kt < 6; kt++) {
                uint32_t a[4];
                ldsm4(a, W2S + ((16 * mt + lsrow) * STW2 + 16 * kt + lscol) * 2);
                mma16816(acc2[mt], a, hfr[kt]);
            }
        }

        // ---- epilogue2: sigmoid -> softmax over {c, c+64, c+128} -> weighted sum ----
        {
            int pxb = n0 + 2 * qcol;
            size_t obase = ((size_t)b << 6) * HWPX + hw0 + pxb;
#pragma unroll
            for (int mt = 0; mt < 4; mt++) {
#pragma unroll
                for (int j = 0; j < 2; j++) {
                    int c = 16 * mt + qrow + 8 * j;
                    float l0 = Xg[c], l1 = Xg[c + 64], l2 = Xg[c + 128];
                    float e00 = exp01(sigm(acc2[mt][2 * j] + l0));
                    float e01 = exp01(sigm(acc2[mt][2 * j + 1] + l0));
                    float e10 = exp01(sigm(acc2[mt + 4][2 * j] + l1));
                    float e11 = exp01(sigm(acc2[mt + 4][2 * j + 1] + l1));
                    float e20 = exp01(sigm(acc2[mt + 8][2 * j] + l2));
                    float e21 = exp01(sigm(acc2[mt + 8][2 * j + 1] + l2));
                    float2 xa = *(const float2*)(XF + c * 64 + pxb);
                    float2 xb = *(const float2*)(XF + (c + 64) * 64 + pxb);
                    float2 xc = *(const float2*)(XF + (c + 128) * 64 + pxb);
                    float i0 = __fdividef(1.f, e00 + e10 + e20);
                    float i1 = __fdividef(1.f, e01 + e11 + e21);
                    float2 r;
                    r.x = (e00 * xa.x + e10 * xb.x + e20 * xc.x) * i0;
                    r.y = (e01 * xa.y + e11 * xb.y + e21 * xc.y) * i1;
                    *(float2*)(out + obase + (size_t)c * HWPX) = r;
                }
            }
        }
        __syncthreads();
    }
}

extern "C" void kernel_launch(void* const* d_in, const int* in_sizes, int n_in,
                              void* d_out, int out_size) {
    const float* x1 = (const float*)d_in[0];
    const float* x2 = (const float*)d_in[1];
    const float* x3 = (const float*)d_in[2];
    const float* lw1 = (const float*)d_in[3];
    const float* lb1 = (const float*)d_in[4];
    const float* lg1 = (const float*)d_in[5];
    const float* lbe1 = (const float*)d_in[6];
    const float* lm1 = (const float*)d_in[7];
    const float* lv1 = (const float*)d_in[8];
    const float* lw2 = (const float*)d_in[9];
    const float* lb2 = (const float*)d_in[10];
    const float* lg2 = (const float*)d_in[11];
    const float* lbe2 = (const float*)d_in[12];
    const float* lm2 = (const float*)d_in[13];
    const float* lv2 = (const float*)d_in[14];
    const float* gw1 = (const float*)d_in[15];
    const float* gb1 = (const float*)d_in[16];
    const float* gg1 = (const float*)d_in[17];
    const float* gbe1 = (const float*)d_in[18];
    const float* gm1 = (const float*)d_in[19];
    const float* gv1 = (const float*)d_in[20];
    const float* gw2 = (const float*)d_in[21];
    const float* gb2 = (const float*)d_in[22];
    const float* gg2 = (const float*)d_in[23];
    const float* gbe2 = (const float*)d_in[24];
    const float* gm2 = (const float*)d_in[25];
    const float* gv2 = (const float*)d_in[26];
    float* out = (float*)d_out;

    cudaFuncSetAttribute(main_kernel, cudaFuncAttributeMaxDynamicSharedMemorySize, DSZ);

    gap_kernel<<<dim3(192, BATCH), 256>>>(x1, x2, x3);
    gmlp_kernel<<<BATCH, 192>>>(gw1, gb1, gg1, gbe1, gm1, gv1,
                                gw2, gb2, gg2, gbe2, gm2, gv2);
    main_kernel<<<NCTA, 256, DSZ>>>(x1, x2, x3,
                                    lw1, lb1, lg1, lbe1, lm1, lv1,
                                    lw2, lb2, lg2, lbe2, lm2, lv2, out);
}